// round 13
// baseline (speedup 1.0000x reference)
#include <cuda_runtime.h>
#include <cuda_fp16.h>
#include <math.h>

#define G      2          // graphs per block
#define NODES  40         // G*20
#define NPG    20
#define HID    128
#define INDIM  9
#define KNN    5
#define H1S    132        // fp32 scratch stride (floats)
#define ABS    136        // fp16 activation stride (elements), GEMM2 plane
#define XAS    40         // fp16 xagg stride (halfs)

typedef unsigned int u32;

// Fused layer-1 weight: Wfused = We@W1 (9x128), bfused = 5*be@W1 + b1
__device__ float g_Wfused[INDIM * HID];
__device__ float g_bfused[HID];

// mma A-operand fragments, fp16 hi/lo planes.
__device__ u32 g_Wf1Hi[1024];
__device__ u32 g_Wf1Lo[1024];
__device__ u32 g_Wf2Hi[8192];
__device__ u32 g_Wf2Lo[8192];

__global__ void prep_fuse(const float* __restrict__ w_embed,
                          const float* __restrict__ b_embed,
                          const float* __restrict__ w1,
                          const float* __restrict__ b1) {
    int c = blockIdx.x * blockDim.x + threadIdx.x;
    if (c >= HID) return;
    #pragma unroll 1
    for (int j = 0; j < INDIM; ++j) {
        float s = 0.0f;
        for (int k = 0; k < HID; ++k)
            s = fmaf(w_embed[j * HID + k], w1[k * HID + c], s);
        g_Wfused[j * HID + c] = s;
    }
    float sb = 0.0f;
    for (int k = 0; k < HID; ++k)
        sb = fmaf(b_embed[k], w1[k * HID + c], sb);
    g_bfused[c] = 5.0f * sb + b1[c];
}

__global__ void prep_wfrag1() {
    int t = blockIdx.x * blockDim.x + threadIdx.x;   // 0..255
    if (t >= 256) return;
    int mt = t >> 5, l = t & 31;
    int gr = l >> 2, tig = l & 3;
    int base = (mt * 32 + l) * 4;
    #pragma unroll
    for (int r = 0; r < 4; ++r) {
        int row = gr + ((r & 1) ? 8 : 0);
        int kb  = tig * 2 + ((r >= 2) ? 8 : 0);
        int m = mt * 16 + row, k = kb;
        float v0 = (k     < INDIM) ? g_Wfused[k * HID + m]       : 0.0f;
        float v1 = (k + 1 < INDIM) ? g_Wfused[(k + 1) * HID + m] : 0.0f;
        __half h0 = __float2half(v0), h1 = __float2half(v1);
        float l0 = v0 - __half2float(h0), l1 = v1 - __half2float(h1);
        __half2 hi; hi.x = h0; hi.y = h1;
        __half2 lo; lo.x = __float2half(l0); lo.y = __float2half(l1);
        g_Wf1Hi[base + r] = *(u32*)&hi;
        g_Wf1Lo[base + r] = *(u32*)&lo;
    }
}

__global__ void prep_wfrag2(const float* __restrict__ w2) {
    int t = blockIdx.x * blockDim.x + threadIdx.x;   // 0..2047
    if (t >= 2048) return;
    int mt = t >> 8, kt = (t >> 5) & 7, l = t & 31;
    int gr = l >> 2, tig = l & 3;
    int base = ((mt * 8 + kt) * 32 + l) * 4;
    #pragma unroll
    for (int r = 0; r < 4; ++r) {
        int row = gr + ((r & 1) ? 8 : 0);
        int kb  = tig * 2 + ((r >= 2) ? 8 : 0);
        int m = mt * 16 + row, k = kt * 16 + kb;
        float v0 = w2[k * HID + m], v1 = w2[(k + 1) * HID + m];
        __half h0 = __float2half(v0), h1 = __float2half(v1);
        float l0 = v0 - __half2float(h0), l1 = v1 - __half2float(h1);
        __half2 hi; hi.x = h0; hi.y = h1;
        __half2 lo; lo.x = __float2half(l0); lo.y = __float2half(l1);
        g_Wf2Hi[base + r] = *(u32*)&hi;
        g_Wf2Lo[base + r] = *(u32*)&lo;
    }
}

__device__ __forceinline__ float gelu_exact(float x) {
    return 0.5f * x * (1.0f + erff(x * 0.70710678118654752440f));
}

#define MMA(d, a, b0v, b1v)                                                       \
    asm volatile("mma.sync.aligned.m16n8k16.row.col.f32.f16.f16.f32 "              \
                 "{%0,%1,%2,%3},{%4,%5,%6,%7},{%8,%9},{%0,%1,%2,%3};"              \
                 : "+f"(d[0]), "+f"(d[1]), "+f"(d[2]), "+f"(d[3])                  \
                 : "r"(a[0]), "r"(a[1]), "r"(a[2]), "r"(a[3]), "r"(b0v), "r"(b1v))

// Layer-1 fused GEMM: K=16 (9 real), X = xagg hi/lo planes, 3 mma terms.
__device__ __forceinline__ void gemm1p(const __half* __restrict__ XsHi,
                                       const __half* __restrict__ XsLo,
                                       int mgroup, int lane,
                                       float acc[2][5][4]) {
    const int gr = lane >> 2, tig = lane & 3;
    u32 ah[2][4], al[2][4];
    #pragma unroll
    for (int mt = 0; mt < 2; ++mt) {
        int idx = ((mgroup * 2 + mt) * 32 + lane) * 4;
        uint4 h = *(const uint4*)&g_Wf1Hi[idx];
        ah[mt][0] = h.x; ah[mt][1] = h.y; ah[mt][2] = h.z; ah[mt][3] = h.w;
        uint4 lo = *(const uint4*)&g_Wf1Lo[idx];
        al[mt][0] = lo.x; al[mt][1] = lo.y; al[mt][2] = lo.z; al[mt][3] = lo.w;
    }
    #pragma unroll
    for (int mt = 0; mt < 2; ++mt)
        #pragma unroll
        for (int nt = 0; nt < 5; ++nt)
            #pragma unroll
            for (int r = 0; r < 4; ++r) acc[mt][nt][r] = 0.0f;
    #pragma unroll
    for (int nt = 0; nt < 5; ++nt) {
        int n0 = nt * 8 + gr;
        u32 bh0 = *(const u32*)(XsHi + n0 * XAS + 2 * tig);
        u32 bh1 = *(const u32*)(XsHi + n0 * XAS + 2 * tig + 8);
        u32 bl0 = *(const u32*)(XsLo + n0 * XAS + 2 * tig);
        u32 bl1 = *(const u32*)(XsLo + n0 * XAS + 2 * tig + 8);
        #pragma unroll
        for (int mt = 0; mt < 2; ++mt) {
            MMA(acc[mt][nt], ah[mt], bh0, bh1);
            MMA(acc[mt][nt], al[mt], bh0, bh1);
            MMA(acc[mt][nt], ah[mt], bl0, bl1);
        }
    }
}

// Layer-2 GEMM: W2 = Wh+Wl fp16 planes vs single fp16 activation plane.
__device__ __forceinline__ void gemm2(const __half* __restrict__ Xs,
                                      int mgroup, int lane,
                                      float acc[2][5][4]) {
    const int gr = lane >> 2, tig = lane & 3;
    #pragma unroll
    for (int mt = 0; mt < 2; ++mt)
        #pragma unroll
        for (int nt = 0; nt < 5; ++nt)
            #pragma unroll
            for (int r = 0; r < 4; ++r) acc[mt][nt][r] = 0.0f;
    #pragma unroll
    for (int kt = 0; kt < 8; ++kt) {
        u32 ah[2][4], al[2][4];
        #pragma unroll
        for (int mt = 0; mt < 2; ++mt) {
            int idx = (((mgroup * 2 + mt) * 8 + kt) * 32 + lane) * 4;
            uint4 h = *(const uint4*)&g_Wf2Hi[idx];
            ah[mt][0] = h.x; ah[mt][1] = h.y; ah[mt][2] = h.z; ah[mt][3] = h.w;
            uint4 lo = *(const uint4*)&g_Wf2Lo[idx];
            al[mt][0] = lo.x; al[mt][1] = lo.y; al[mt][2] = lo.z; al[mt][3] = lo.w;
        }
        u32 bh[5][2];
        const int kb = kt * 16 + 2 * tig;
        #pragma unroll
        for (int nt = 0; nt < 5; ++nt) {
            int n0 = nt * 8 + gr;
            bh[nt][0] = *(const u32*)(Xs + n0 * ABS + kb);
            bh[nt][1] = *(const u32*)(Xs + n0 * ABS + kb + 8);
        }
        #pragma unroll
        for (int mt = 0; mt < 2; ++mt)
            #pragma unroll
            for (int nt = 0; nt < 5; ++nt) {
                MMA(acc[mt][nt], ah[mt], bh[nt][0], bh[nt][1]);
                MMA(acc[mt][nt], al[mt], bh[nt][0], bh[nt][1]);
            }
    }
}

// Shared LN stats: partials -> smem -> combine. All 128 threads participate.
__device__ __forceinline__ void ln_stats(float acc[2][5][4],
                                         const float bA[2], const float bB[2],
                                         float* pSum, float* pSq,
                                         float* meanv, float* rstdv,
                                         int mgroup, int lane) {
    const int gr = lane >> 2, tig = lane & 3;
    #pragma unroll
    for (int nt = 0; nt < 5; ++nt) {
        float sA = 0, sB = 0, qA = 0, qB = 0;
        #pragma unroll
        for (int mt = 0; mt < 2; ++mt) {
            float x0 = acc[mt][nt][0] + bA[mt];
            float x1 = acc[mt][nt][1] + bA[mt];
            float x2 = acc[mt][nt][2] + bB[mt];
            float x3 = acc[mt][nt][3] + bB[mt];
            sA += x0 + x2; sB += x1 + x3;
            qA += x0 * x0 + x2 * x2; qB += x1 * x1 + x3 * x3;
        }
        #pragma unroll
        for (int off = 4; off <= 16; off <<= 1) {
            sA += __shfl_xor_sync(0xffffffffu, sA, off);
            sB += __shfl_xor_sync(0xffffffffu, sB, off);
            qA += __shfl_xor_sync(0xffffffffu, qA, off);
            qB += __shfl_xor_sync(0xffffffffu, qB, off);
        }
        if (gr == 0) {
            int nA = nt * 8 + 2 * tig;
            pSum[mgroup * NODES + nA]     = sA;
            pSum[mgroup * NODES + nA + 1] = sB;
            pSq [mgroup * NODES + nA]     = qA;
            pSq [mgroup * NODES + nA + 1] = qB;
        }
    }
    __syncthreads();
    if (threadIdx.x < NODES) {
        int n = threadIdx.x;
        float S = pSum[n] + pSum[NODES + n] + pSum[2 * NODES + n] + pSum[3 * NODES + n];
        float Q = pSq[n]  + pSq[NODES + n]  + pSq[2 * NODES + n]  + pSq[3 * NODES + n];
        float m = S * (1.0f / 128.0f);
        float var = fmaxf(Q * (1.0f / 128.0f) - m * m, 0.0f);
        meanv[n] = m;
        rstdv[n] = rsqrtf(var + 1e-5f);
    }
    __syncthreads();
}

// aggregate over knn neighbors from fp32 h1f (float4), write single fp16 plane.
__device__ __forceinline__ void agg_split(const float* __restrict__ h1f,
                                          const int* __restrict__ nbr,
                                          __half* __restrict__ Xs, int t) {
    #pragma unroll
    for (int i = 0; i < 10; ++i) {
        int q = t + 128 * i;              // 1280 quads
        int n = q >> 5;                   // warp-uniform node
        int fq = (q & 31) * 4;
        const int* nb = &nbr[n * KNN];
        float4 s = make_float4(0.f, 0.f, 0.f, 0.f);
        #pragma unroll
        for (int r = 0; r < KNN; ++r) {
            float4 a = *(const float4*)(h1f + nb[r] * H1S + fq);
            s.x += a.x; s.y += a.y; s.z += a.z; s.w += a.w;
        }
        __half2 p0 = __floats2half2_rn(s.x, s.y);
        __half2 p1 = __floats2half2_rn(s.z, s.w);
        uint2 pk; pk.x = *(u32*)&p0; pk.y = *(u32*)&p1;
        *(uint2*)(Xs + n * ABS + fq) = pk;
    }
}

#define SMEM_BYTES 34400

__global__ __launch_bounds__(128, 4)
void hbond_gnn_mma(const float* __restrict__ x_all,
                   const float* __restrict__ g1,
                   const float* __restrict__ be1,
                   const float* __restrict__ b2,
                   const float* __restrict__ g2,
                   const float* __restrict__ be2,
                   float* __restrict__ out) {
    extern __shared__ char smem[];
    // h1f is written only from epilogue-1 onward; xs/d2s alias its space (dead by then).
    float* h1f   = (float*)smem;                        // 40*132*4 = 21120
    float* xs    = (float*)smem;                        // 360*4 = 1440 (alias)
    float* d2s   = (float*)(smem + 1440);               // 800*4 = 3200 (alias)
    __half* Xs   = (__half*)(smem + 21120);             // 40*136*2 = 10880 (GEMM2 plane)
    __half* XsHi = (__half*)(smem + 21120);             // 40*40*2 = 3200 (alias)
    __half* XsLo = (__half*)(smem + 24320);             // 3200 (alias)
    int*   nbr   = (int*)(smem + 32000);                // 200*4 = 800
    float* pSum  = (float*)(smem + 32800);              // 160*4 = 640
    float* pSq   = (float*)(smem + 33440);              // 640
    float* meanv = (float*)(smem + 34080);              // 160
    float* rstdv = (float*)(smem + 34240);              // 160

    const int t = threadIdx.x;
    const int lane = t & 31;
    const int mgroup = t >> 5;                           // warp = m-group (0..3)
    const int gr = lane >> 2, tig = lane & 3;
    const float* x = x_all + (size_t)blockIdx.x * (NODES * INDIM);

    // ---- node features ----
    for (int i = t; i < NODES * INDIM; i += 128) xs[i] = x[i];
    __syncthreads();

    // ---- pairwise d2 per graph ----
    for (int i = t; i < G * NPG * NPG; i += 128) {
        int g = i / 400, rem = i % 400;
        int a = rem / NPG, bb = rem % NPG;
        const float* pa = &xs[(g * NPG + a) * INDIM + 6];
        const float* pb = &xs[(g * NPG + bb) * INDIM + 6];
        float dx = pa[0] - pb[0], dy = pa[1] - pb[1], dz = pa[2] - pb[2];
        d2s[i] = (dx * dx + dy * dy) + dz * dz;
    }
    __syncthreads();

    // ---- top-5 (ties -> lower index) + xagg (exact fp32 agg of raw features) ----
    if (t < NODES) {
        int g = t / NPG, i = t % NPG;
        const float* row = &d2s[g * 400 + i * NPG];
        unsigned mask = 0;
        int nb[KNN];
        for (int r = 0; r < KNN; ++r) {
            float best = 3.4e38f; int bj = 0;
            #pragma unroll
            for (int j = 0; j < NPG; ++j) {
                float v = row[j];
                if (!((mask >> j) & 1u) && v < best) { best = v; bj = j; }
            }
            mask |= 1u << bj;
            nb[r] = g * NPG + bj;
            nbr[t * KNN + r] = nb[r];
        }
        __half* hi = XsHi + t * XAS;
        __half* lo = XsLo + t * XAS;
        #pragma unroll
        for (int j = 0; j < INDIM; ++j) {
            float s = 0.0f;
            #pragma unroll
            for (int r = 0; r < KNN; ++r) s += xs[nb[r] * INDIM + j];
            __half h = __float2half(s);
            hi[j] = h;
            lo[j] = __float2half(s - __half2float(h));
        }
        const __half z = __float2half(0.0f);
        #pragma unroll
        for (int j = INDIM; j < 16; ++j) { hi[j] = z; lo[j] = z; }
    }
    __syncthreads();

    float acc[2][5][4];
    float bA[2], bB[2];

    // ==== fused layer 1: (adj@x)@(We@W1) + bfused -> LN1 -> gelu -> h1f ====
    gemm1p(XsHi, XsLo, mgroup, lane, acc);
    #pragma unroll
    for (int mt = 0; mt < 2; ++mt) {
        int f0 = mgroup * 32 + mt * 16 + gr;
        bA[mt] = g_bfused[f0]; bB[mt] = g_bfused[f0 + 8];
    }
    ln_stats(acc, bA, bB, pSum, pSq, meanv, rstdv, mgroup, lane);
    {
        #pragma unroll
        for (int nt = 0; nt < 5; ++nt) {
            int nA = nt * 8 + 2 * tig, nB = nA + 1;
            float mA = meanv[nA], mB = meanv[nB];
            float rA = rstdv[nA], rB = rstdv[nB];
            #pragma unroll
            for (int mt = 0; mt < 2; ++mt) {
                int f0 = mgroup * 32 + mt * 16 + gr;
                float gA = g1[f0], gB = g1[f0 + 8];
                float eA = be1[f0], eB = be1[f0 + 8];
                float x0 = acc[mt][nt][0] + bA[mt];
                float x1 = acc[mt][nt][1] + bA[mt];
                float x2 = acc[mt][nt][2] + bB[mt];
                float x3 = acc[mt][nt][3] + bB[mt];
                float* pA0 = h1f + nA * H1S + f0;
                float* pB0 = h1f + nB * H1S + f0;
                pA0[0] = gelu_exact(fmaf((x0 - mA) * rA, gA, eA));
                pB0[0] = gelu_exact(fmaf((x1 - mB) * rB, gA, eA));
                pA0[8] = gelu_exact(fmaf((x2 - mA) * rA, gB, eB));
                pB0[8] = gelu_exact(fmaf((x3 - mB) * rB, gB, eB));
            }
        }
    }
    __syncthreads();

    // ==== agg2 -> Xs (fp16) ====
    agg_split(h1f, nbr, Xs, t);
    __syncthreads();

    // ==== GEMM2 -> LN2 -> residual -> gelu -> fused per-graph max -> STG ====
    gemm2(Xs, mgroup, lane, acc);
    #pragma unroll
    for (int mt = 0; mt < 2; ++mt) {
        int f0 = mgroup * 32 + mt * 16 + gr;
        bA[mt] = b2[f0]; bB[mt] = b2[f0 + 8];
    }
    ln_stats(acc, bA, bB, pSum, pSq, meanv, rstdv, mgroup, lane);
    {
        float mx[2][2][2];   // [graph][mt][feature pair]
        #pragma unroll
        for (int gph = 0; gph < 2; ++gph)
            #pragma unroll
            for (int mt = 0; mt < 2; ++mt)
                mx[gph][mt][0] = mx[gph][mt][1] = -3.4e38f;

        #pragma unroll
        for (int nt = 0; nt < 5; ++nt) {
            int nA = nt * 8 + 2 * tig, nB = nA + 1;
            int gph = (nA >= NPG) ? 1 : 0;   // nA,nB always in same graph (nA even)
            float mA = meanv[nA], mB = meanv[nB];
            float rA = rstdv[nA], rB = rstdv[nB];
            #pragma unroll
            for (int mt = 0; mt < 2; ++mt) {
                int f0 = mgroup * 32 + mt * 16 + gr;
                float gA = g2[f0], gB = g2[f0 + 8];
                float eA = be2[f0], eB = be2[f0 + 8];
                float x0 = acc[mt][nt][0] + bA[mt];
                float x1 = acc[mt][nt][1] + bA[mt];
                float x2 = acc[mt][nt][2] + bB[mt];
                float x3 = acc[mt][nt][3] + bB[mt];
                const float* pA0 = h1f + nA * H1S + f0;
                const float* pB0 = h1f + nB * H1S + f0;
                float v0 = gelu_exact(pA0[0] + fmaf((x0 - mA) * rA, gA, eA));
                float v1 = gelu_exact(pB0[0] + fmaf((x1 - mB) * rB, gA, eA));
                float v2 = gelu_exact(pA0[8] + fmaf((x2 - mA) * rA, gB, eB));
                float v3 = gelu_exact(pB0[8] + fmaf((x3 - mB) * rB, gB, eB));
                mx[gph][mt][0] = fmaxf(mx[gph][mt][0], fmaxf(v0, v1));
                mx[gph][mt][1] = fmaxf(mx[gph][mt][1], fmaxf(v2, v3));
            }
        }
        // combine across tig lanes (same gr, same features)
        #pragma unroll
        for (int gph = 0; gph < 2; ++gph)
            #pragma unroll
            for (int mt = 0; mt < 2; ++mt)
                #pragma unroll
                for (int p = 0; p < 2; ++p) {
                    float v = mx[gph][mt][p];
                    v = fmaxf(v, __shfl_xor_sync(0xffffffffu, v, 1));
                    v = fmaxf(v, __shfl_xor_sync(0xffffffffu, v, 2));
                    mx[gph][mt][p] = v;
                }
        if (tig == 0) {
            float* og = out + (size_t)blockIdx.x * (G * HID);
            #pragma unroll
            for (int gph = 0; gph < 2; ++gph)
                #pragma unroll
                for (int mt = 0; mt < 2; ++mt) {
                    int f0 = mgroup * 32 + mt * 16 + gr;
                    og[gph * HID + f0]     = mx[gph][mt][0];
                    og[gph * HID + f0 + 8] = mx[gph][mt][1];
                }
        }
    }
}

extern "C" void kernel_launch(void* const* d_in, const int* in_sizes, int n_in,
                              void* d_out, int out_size) {
    const float* x_all   = (const float*)d_in[0];
    const float* w_embed = (const float*)d_in[1];
    const float* b_embed = (const float*)d_in[2];
    const float* w1      = (const float*)d_in[3];
    const float* b1      = (const float*)d_in[4];
    const float* w2      = (const float*)d_in[5];
    const float* b2      = (const float*)d_in[6];
    const float* g1      = (const float*)d_in[7];
    const float* be1     = (const float*)d_in[8];
    const float* g2      = (const float*)d_in[9];
    const float* be2     = (const float*)d_in[10];
    float* out = (float*)d_out;

    const int B = in_sizes[0] / (NPG * INDIM);

    static int attr_set = 0;
    if (!attr_set) {
        cudaFuncSetAttribute(hbond_gnn_mma,
                             cudaFuncAttributeMaxDynamicSharedMemorySize, SMEM_BYTES);
        attr_set = 1;
    }

    prep_fuse<<<1, 128>>>(w_embed, b_embed, w1, b1);
    prep_wfrag1<<<1, 256>>>();
    prep_wfrag2<<<8, 256>>>(w2);
    hbond_gnn_mma<<<B / G, 128, SMEM_BYTES>>>(x_all, g1, be1, b2, g2, be2, out);
}